// round 15
// baseline (speedup 1.0000x reference)
#include <cuda_runtime.h>
#include <cuda_fp16.h>
#include <cstdint>

#define BATCH 8
#define HW    1024
#define QKV_CH 768

// Scratch (device globals; no allocation allowed)
__device__ __half g_xh    [BATCH * 512 * HW];   // x in fp16
__device__ __half g_wqkvh [QKV_CH * 512];       // w_qkv fp16
__device__ __half g_wattnh[512 * 256];          // w_attn fp16
__device__ __half g_qkvh  [BATCH * QKV_CH * HW];
__device__ __half g_afh   [BATCH * 256 * HW];   // attention out, scrambled layout

// ===========================================================================
// helpers
// ===========================================================================
__device__ __forceinline__ uint32_t smem_u32(const void* p) {
    uint32_t a;
    asm("{ .reg .u64 t; cvta.to.shared.u64 t, %1; cvt.u32.u64 %0, t; }"
        : "=r"(a) : "l"(p));
    return a;
}
__device__ __forceinline__ void mma16816(float* c, const uint32_t* a, const uint32_t* b) {
    asm volatile("mma.sync.aligned.m16n8k16.row.col.f32.f16.f16.f32 "
        "{%0,%1,%2,%3}, {%4,%5,%6,%7}, {%8,%9}, {%0,%1,%2,%3};"
        : "+f"(c[0]), "+f"(c[1]), "+f"(c[2]), "+f"(c[3])
        : "r"(a[0]), "r"(a[1]), "r"(a[2]), "r"(a[3]), "r"(b[0]), "r"(b[1]));
}
__device__ __forceinline__ void ldsm_x4(uint32_t* r, uint32_t addr) {
    asm volatile("ldmatrix.sync.aligned.m8n8.x4.shared.b16 {%0,%1,%2,%3}, [%4];"
        : "=r"(r[0]), "=r"(r[1]), "=r"(r[2]), "=r"(r[3]) : "r"(addr));
}
__device__ __forceinline__ void ldsm_x4t(uint32_t* r, uint32_t addr) {
    asm volatile("ldmatrix.sync.aligned.m8n8.x4.trans.shared.b16 {%0,%1,%2,%3}, [%4];"
        : "=r"(r[0]), "=r"(r[1]), "=r"(r[2]), "=r"(r[3]) : "r"(addr));
}
__device__ __forceinline__ uint32_t pack_h2(float lo, float hi) {
    __half2 h = __floats2half2_rn(lo, hi);
    return *reinterpret_cast<uint32_t*>(&h);
}
__device__ __forceinline__ uint32_t hh2pack(__half a, __half b) {
    __half2 h = __halves2half2(a, b);
    return *reinterpret_cast<uint32_t*>(&h);
}
__device__ __forceinline__ float2 h2f2(uint32_t u) {
    __half2 h = *reinterpret_cast<__half2*>(&u);
    return __half22float2(h);
}
__device__ __forceinline__ uint32_t hmul2(uint32_t a, uint32_t b) {
    uint32_t d;
    asm("mul.rn.f16x2 %0, %1, %2;" : "=r"(d) : "r"(a), "r"(b));
    return d;
}
__device__ __forceinline__ uint32_t hadd2(uint32_t a, uint32_t b) {
    uint32_t d;
    asm("add.rn.f16x2 %0, %1, %2;" : "=r"(d) : "r"(a), "r"(b));
    return d;
}
// MUFU packed fp16 exp2 (valid at sm_103 generic)
__device__ __forceinline__ uint32_t hex2(uint32_t a) {
    uint32_t d;
    asm("ex2.approx.f16x2 %0, %1;" : "=r"(d) : "r"(a));
    return d;
}
__device__ __forceinline__ float frcpa(float x) {
    float r; asm("rcp.approx.f32 %0, %1;" : "=f"(r) : "f"(x)); return r;
}
// packed reciprocal via 2x f32 MUFU rcp (f16x2 rcp not supported at sm_103)
__device__ __forceinline__ uint32_t hrcp2(uint32_t a) {
    float2 f = h2f2(a);
    return pack_h2(frcpa(f.x), frcpa(f.y));
}
#define CP_ASYNC16(dst, src) \
    asm volatile("cp.async.cg.shared.global [%0], [%1], 16;" \
                 :: "r"(dst), "l"(src) : "memory")
#define CP_COMMIT() asm volatile("cp.async.commit_group;" ::: "memory")
#define CP_WAIT1()  asm volatile("cp.async.wait_group 1;" ::: "memory")
#define GROUP_BAR64(id) asm volatile("bar.sync %0, 64;" :: "r"(id) : "memory")

// ===========================================================================
// fused fp32 -> fp16 conversion for x, w_qkv, w_attn (one launch)
// ===========================================================================
static constexpr int N4_X  = 1048576;
static constexpr int N4_WQ = 98304;
static constexpr int N4_WA = 32768;
static constexpr int N4_ALL = N4_X + N4_WQ + N4_WA;

__global__ void f2h_all(const float* __restrict__ x, const float* __restrict__ wq,
                        const float* __restrict__ wa,
                        __half* __restrict__ xh, __half* __restrict__ wqh,
                        __half* __restrict__ wah)
{
    int i = blockIdx.x * blockDim.x + threadIdx.x;
    const float* src;
    __half* dst;
    int j;
    if (i < N4_X)                 { src = x;  dst = xh;  j = i; }
    else if (i < N4_X + N4_WQ)    { src = wq; dst = wqh; j = i - N4_X; }
    else if (i < N4_ALL)          { src = wa; dst = wah; j = i - N4_X - N4_WQ; }
    else return;
    float4 v = ((const float4*)src)[j];
    uint2 p;
    p.x = pack_h2(v.x, v.y);
    p.y = pack_h2(v.z, v.w);
    ((uint2*)dst)[j] = p;
}

// ===========================================================================
// all-fp16 mma.sync GEMM, BK=64, cp.async 3-stage, 2 CTAs/SM.
// A stage: [128 m][72 halves] (144B rows, slot=9r+c -> conflict-free ldsm).
// B stage: [64 k][136 halves] (272B rows). 8 warps (2m x 4n), warp 64x32.
// ===========================================================================
static constexpr int GASZ = 128 * 144;    // 18432 B
static constexpr int GBSZ = 64 * 272;     // 17408 B
static constexpr int GSTG = GASZ + GBSZ;  // 35840 B
static constexpr int GEMM_SMEM = 3 * GSTG;  // 107520 B (2 CTAs/SM)

template<int M, int K, int SCALE_ROWS, typename TY>
__global__ __launch_bounds__(256, 2)
void gemm_mma(const __half* __restrict__ W, const __half* __restrict__ X,
              const float* __restrict__ bias, TY* __restrict__ Y,
              float scaleVal)
{
    extern __shared__ char smraw[];
    const uint32_t smb = smem_u32(smraw);

    const int t    = threadIdx.x;
    const int lane = t & 31;
    const int wid  = t >> 5;
    const int g    = lane >> 2;
    const int t4   = lane & 3;
    const int wm   = (wid & 1) * 64;
    const int wn   = (wid >> 1) * 32;
    const int b    = blockIdx.z;
    const int m0   = blockIdx.y * 128;
    const int n0   = blockIdx.x * 128;
    const __half* Xb = X + (size_t)b * K * 1024;
    TY*           Yb = Y + (size_t)b * M * 1024;

    const int r16 = lane & 15;
    const int c8  = (lane >> 4) * 8;
    const uint32_t aAddr = smb + (wm + r16) * 144 + c8 * 2;
    const uint32_t bAddr = smb + GASZ + r16 * 272 + (wn + c8) * 2;

    const int NC = K / 64;
    auto PRE = [&](int kc) {
        if (kc < NC) {
            const uint32_t so = (uint32_t)(kc % 3) * GSTG;
#pragma unroll
            for (int c = 0; c < 4; c++) {
                int idx = c * 256 + t;
                int ar = idx >> 3, ac = (idx & 7) * 8;       // A: 128r x 8 segs
                CP_ASYNC16(smb + so + ar * 144 + ac * 2,
                           W + (size_t)(m0 + ar) * K + kc * 64 + ac);
                int br = idx >> 4, bc = (idx & 15) * 8;      // B: 64r x 16 segs
                CP_ASYNC16(smb + so + GASZ + br * 272 + bc * 2,
                           Xb + (size_t)(kc * 64 + br) * 1024 + n0 + bc);
            }
        }
        CP_COMMIT();
    };

    float acc[4][4][4];
#pragma unroll
    for (int i = 0; i < 4; i++)
#pragma unroll
        for (int j = 0; j < 4; j++)
#pragma unroll
            for (int q = 0; q < 4; q++) acc[i][j][q] = 0.f;

    PRE(0);
    PRE(1);

    for (int kc = 0; kc < NC; kc++) {
        CP_WAIT1();
        __syncthreads();
        PRE(kc + 2);

        const uint32_t so = (uint32_t)(kc % 3) * GSTG;
        const uint32_t aB = aAddr + so;
        const uint32_t bB = bAddr + so;
#pragma unroll
        for (int s = 0; s < 4; s++) {
            uint32_t afr[4][4], bfr[2][4];
#pragma unroll
            for (int mf = 0; mf < 4; mf++)
                ldsm_x4(afr[mf], aB + mf * 16 * 144 + s * 32);
#pragma unroll
            for (int np = 0; np < 2; np++)
                ldsm_x4t(bfr[np], bB + np * 32 + s * 16 * 272);
#pragma unroll
            for (int mf = 0; mf < 4; mf++)
#pragma unroll
                for (int np = 0; np < 2; np++) {
                    mma16816(acc[mf][2 * np],     afr[mf], bfr[np] + 0);
                    mma16816(acc[mf][2 * np + 1], afr[mf], bfr[np] + 2);
                }
        }
    }

#pragma unroll
    for (int mf = 0; mf < 4; mf++) {
        int r0 = m0 + wm + mf * 16 + g;
        int r1 = r0 + 8;
        float b0v = bias[r0], b1v = bias[r1];
        float s0 = (SCALE_ROWS > 0 && r0 < SCALE_ROWS) ? scaleVal : 1.f;
        float s1 = (SCALE_ROWS > 0 && r1 < SCALE_ROWS) ? scaleVal : 1.f;
#pragma unroll
        for (int nf = 0; nf < 4; nf++) {
            int nc = n0 + wn + nf * 8 + 2 * t4;
            if constexpr (sizeof(TY) == 2) {
                *(uint32_t*)&Yb[(size_t)r0 * 1024 + nc] =
                    pack_h2((acc[mf][nf][0] + b0v) * s0, (acc[mf][nf][1] + b0v) * s0);
                *(uint32_t*)&Yb[(size_t)r1 * 1024 + nc] =
                    pack_h2((acc[mf][nf][2] + b1v) * s1, (acc[mf][nf][3] + b1v) * s1);
            } else {
                float2 v0, v1;
                v0.x = (acc[mf][nf][0] + b0v) * s0;
                v0.y = (acc[mf][nf][1] + b0v) * s0;
                v1.x = (acc[mf][nf][2] + b1v) * s1;
                v1.y = (acc[mf][nf][3] + b1v) * s1;
                *(float2*)&Yb[(size_t)r0 * 1024 + nc] = v0;
                *(float2*)&Yb[(size_t)r1 * 1024 + nc] = v1;
            }
        }
    }
}

// ===========================================================================
// fp16 fused attention (unchanged from round 14): in-register head softmax,
// packed-fp16 MUFU softmax (ex2.f16x2, HADD2 denoms, f32-rcp repacked,
// HMUL2 W-repack). Softmax across the 8 HEADS. Output: scrambled reshape.
// ===========================================================================
static constexpr int KS_OFF = 0;                    // 3 x 20480
static constexpr int VS_OFF = 3 * 20480;            // 3 x 20480
static constexpr int PD_OFF = 6 * 20480;            // 8 x 2176
static constexpr int ATTN_SMEM = PD_OFF + 8 * 2176; // 140288 B

__global__ __launch_bounds__(256, 1)
void attn_mma(const __half* __restrict__ qkvh, __half* __restrict__ af)
{
    extern __shared__ char smraw[];
    const uint32_t smb = smem_u32(smraw);

    const int b    = blockIdx.y;
    const int qt   = blockIdx.x;           // 16 tiles of 64 queries
    const int t    = threadIdx.x;
    const int lane = t & 31;
    const int w    = t >> 5;               // 8 warps
    const int p    = w >> 1;               // pair 0..3
    const int wip  = w & 1;                // 0: heads 0-3, 1: heads 4-7
    const int g    = lane >> 2;
    const int t4   = lane & 3;

    const int r16 = lane & 15;
    const int c8  = (lane >> 4) * 8;
    const int r2  = (lane & 7) + (lane >> 4) * 8;
    const int c2  = ((lane >> 3) & 1) * 8;

    const int qW = qt * 64 + p * 16;       // this pair's 16-query slice
    const __half* qbh = qkvh + (size_t)b * QKV_CH * HW;

    // ---- preload Q A-fragments for 4 heads (reused all 32 tiles) ----
    uint32_t qa[4][2][4];
#pragma unroll
    for (int h = 0; h < 4; h++) {
        const int gh = wip * 4 + h;
#pragma unroll
        for (int s = 0; s < 2; s++) {
            int d0 = s * 16 + 2 * t4;
            const __half* ra = qbh + (size_t)(gh * 32 + d0) * HW;
            const __half* rb = qbh + (size_t)(gh * 32 + d0 + 1) * HW;
            const __half* rc = qbh + (size_t)(gh * 32 + d0 + 8) * HW;
            const __half* rd = qbh + (size_t)(gh * 32 + d0 + 9) * HW;
            int qq = qW + g;
            qa[h][s][0] = hh2pack(ra[qq],     rb[qq]);
            qa[h][s][1] = hh2pack(ra[qq + 8], rb[qq + 8]);
            qa[h][s][2] = hh2pack(rc[qq],     rd[qq]);
            qa[h][s][3] = hh2pack(rc[qq + 8], rd[qq + 8]);
        }
    }

    float oacc[4][4][4];                   // [head][d-frag][pos]
#pragma unroll
    for (int i = 0; i < 4; i++)
#pragma unroll
        for (int j = 0; j < 4; j++)
#pragma unroll
            for (int q = 0; q < 4; q++) oacc[i][j][q] = 0.f;

    const uint32_t kRow = smb + KS_OFF + ((wip * 128 + r16) * 40 + c8) * 2;
    const uint32_t vRow = smb + VS_OFF + ((wip * 128 + r2) * 40 + c2) * 2;
    char* pdA = smraw + PD_OFF + (p * 2 + wip) * 2176;        // own partials
    char* pdB = smraw + PD_OFF + (p * 2 + (wip ^ 1)) * 2176;  // partner's

    auto PREFETCH = [&](int kt2) {
        if (kt2 <= 31) {
            const int k0 = kt2 * 32;
            const int bo = (kt2 % 3) * 20480;
#pragma unroll
            for (int c = 0; c < 4; c++) {
                int idx = c * 256 + t;
                int row = idx >> 2;
                int col = (idx & 3) * 8;
                CP_ASYNC16(smb + KS_OFF + bo + row * 80 + col * 2,
                           qbh + (size_t)(256 + row) * HW + k0 + col);
                CP_ASYNC16(smb + VS_OFF + bo + row * 80 + col * 2,
                           qbh + (size_t)(512 + row) * HW + k0 + col);
            }
        }
        CP_COMMIT();
    };

    PREFETCH(0);

    for (int kt = 0; kt < 32; kt++) {
        PREFETCH(kt + 1);
        CP_WAIT1();
        __syncthreads();

        const uint32_t bo = (uint32_t)(kt % 3) * 20480;

        // ---- S + packed-fp16 MUFU exp + HADD2 partial denominators ----
        uint32_t eh[4][4][2];
        uint32_t pd2[4][2];                // half2 partial denoms [nf][rh]
#pragma unroll
        for (int nf = 0; nf < 4; nf++) {
            pd2[nf][0] = 0u;
            pd2[nf][1] = 0u;
        }

#pragma unroll
        for (int h = 0; h < 4; h++) {
            float sacc[4][4];
#pragma unroll
            for (int nf = 0; nf < 4; nf++)
#pragma unroll
                for (int q = 0; q < 4; q++) sacc[nf][q] = 0.f;
#pragma unroll
            for (int np = 0; np < 2; np++)
#pragma unroll
                for (int s = 0; s < 2; s++) {
                    uint32_t bk[4];
                    ldsm_x4t(bk, kRow + bo + h * 2560 + s * 1280 + np * 32);
                    mma16816(sacc[np * 2 + 0], qa[h][s], bk + 0);
                    mma16816(sacc[np * 2 + 1], qa[h][s], bk + 2);
                }
#pragma unroll
            for (int nf = 0; nf < 4; nf++) {
                uint32_t e0 = hex2(pack_h2(sacc[nf][0], sacc[nf][1]));
                uint32_t e1 = hex2(pack_h2(sacc[nf][2], sacc[nf][3]));
                eh[h][nf][0] = e0;
                eh[h][nf][1] = e1;
                pd2[nf][0] = hadd2(pd2[nf][0], e0);
                pd2[nf][1] = hadd2(pd2[nf][1], e1);
            }
        }

        // ---- store own partials, hoist heads 0-1 V frags, pair barrier ----
#pragma unroll
        for (int nf = 0; nf < 4; nf++) {
            *(uint32_t*)(pdA + (g)     * 80 + (nf * 8 + 2 * t4) * 2) = pd2[nf][0];
            *(uint32_t*)(pdA + (g + 8) * 80 + (nf * 8 + 2 * t4) * 2) = pd2[nf][1];
        }
        uint32_t vb01[2][2][2][4];         // [h][ks][db] V frags heads 0,1
#pragma unroll
        for (int h = 0; h < 2; h++)
#pragma unroll
            for (int ks = 0; ks < 2; ks++)
#pragma unroll
                for (int db = 0; db < 2; db++)
                    ldsm_x4(vb01[h][ks][db],
                            vRow + bo + h * 2560 + db * 1280 + ks * 32);

        GROUP_BAR64(1 + p);

        // ---- full denominators (HADD2) -> rcp (2x f32 MUFU, repacked) ----
        uint32_t rcph[4][2];
#pragma unroll
        for (int nf = 0; nf < 4; nf++) {
            uint32_t q0 = *(uint32_t*)(pdB + (g)     * 80 + (nf * 8 + 2 * t4) * 2);
            uint32_t q1 = *(uint32_t*)(pdB + (g + 8) * 80 + (nf * 8 + 2 * t4) * 2);
            rcph[nf][0] = hrcp2(hadd2(pd2[nf][0], q0));
            rcph[nf][1] = hrcp2(hadd2(pd2[nf][1], q1));
        }

        // ---- O += W V (W = eh * rcph via HMUL2; V from smem as B-frags) ----
#pragma unroll
        for (int h = 0; h < 4; h++) {
#pragma unroll
            for (int ks = 0; ks < 2; ks++) {
                uint32_t wfrag[4];
                wfrag[0] = hmul2(eh[h][2 * ks][0],     rcph[2 * ks][0]);
                wfrag[1] = hmul2(eh[h][2 * ks][1],     rcph[2 * ks][1]);
                wfrag[2] = hmul2(eh[h][2 * ks + 1][0], rcph[2 * ks + 1][0]);
                wfrag[3] = hmul2(eh[h][2 * ks + 1][1], rcph[2 * ks + 1][1]);
#pragma unroll
                for (int db = 0; db < 2; db++) {
                    uint32_t vb[4];
                    if (h < 2) {
                        vb[0] = vb01[h][ks][db][0]; vb[1] = vb01[h][ks][db][1];
                        vb[2] = vb01[h][ks][db][2]; vb[3] = vb01[h][ks][db][3];
                    } else {
                        ldsm_x4(vb, vRow + bo + h * 2560 + db * 1280 + ks * 32);
                    }
                    mma16816(oacc[h][db * 2 + 0], wfrag, vb + 0);
                    mma16816(oacc[h][db * 2 + 1], wfrag, vb + 2);
                }
            }
        }
    }

    // ---- epilogue: scrambled flat-reshape layout, fp16 ----
#pragma unroll
    for (int h = 0; h < 4; h++) {
        const int gh = wip * 4 + h;
        __half* ob = af + ((size_t)(b * 256 + gh * 32 + qt * 2 + (p >> 1))) * 1024
                     + (p & 1) * 512;
#pragma unroll
        for (int nd = 0; nd < 4; nd++) {
#pragma unroll
            for (int rh = 0; rh < 2; rh++) {
                int col = (g + 8 * rh) * 32 + nd * 8 + 2 * t4;
                *(uint32_t*)(ob + col) =
                    pack_h2(oacc[h][nd][rh * 2 + 0], oacc[h][nd][rh * 2 + 1]);
            }
        }
    }
}

// ---------------------------------------------------------------------------
extern "C" void kernel_launch(void* const* d_in, const int* in_sizes, int n_in,
                              void* d_out, int out_size)
{
    const float* x      = (const float*)d_in[0];   // [8,512,32,32]
    const float* w_qkv  = (const float*)d_in[1];   // [768,512]
    const float* b_qkv  = (const float*)d_in[2];   // [768]
    const float* w_attn = (const float*)d_in[3];   // [512,256]
    const float* b_attn = (const float*)d_in[4];   // [512]
    float* out = (float*)d_out;                    // [8,512,32,32]

    void *xh, *wqh, *wah, *qkvp, *afp;
    cudaGetSymbolAddress(&xh,   g_xh);
    cudaGetSymbolAddress(&wqh,  g_wqkvh);
    cudaGetSymbolAddress(&wah,  g_wattnh);
    cudaGetSymbolAddress(&qkvp, g_qkvh);
    cudaGetSymbolAddress(&afp,  g_afh);

    cudaFuncSetAttribute((const void*)gemm_mma<768, 512, 256, __half>,
                         cudaFuncAttributeMaxDynamicSharedMemorySize, GEMM_SMEM);
    cudaFuncSetAttribute((const void*)gemm_mma<512, 256, 0, float>,
                         cudaFuncAttributeMaxDynamicSharedMemorySize, GEMM_SMEM);
    cudaFuncSetAttribute((const void*)attn_mma,
                         cudaFuncAttributeMaxDynamicSharedMemorySize, ATTN_SMEM);

    // 0) fused fp32 -> fp16 conversion (x, w_qkv, w_attn)
    f2h_all<<<(N4_ALL + 255) / 256, 256>>>(x, w_qkv, w_attn,
                                           (__half*)xh, (__half*)wqh, (__half*)wah);

    // 1) QKV projection; q rows pre-scaled by dkh^-0.5 * log2(e) so the
    //    attention exp is a bare ex2.
    gemm_mma<768, 512, 256, __half><<<dim3(8, 6, BATCH), 256, GEMM_SMEM>>>(
        (const __half*)wqh, (const __half*)xh, b_qkv, (__half*)qkvp,
        0.17677669529663687f * 1.4426950408889634f);

    // 2) fp16 fused attention, packed-fp16 MUFU softmax
    attn_mma<<<dim3(16, BATCH), 256, ATTN_SMEM>>>((const __half*)qkvp,
                                                  (__half*)afp);

    // 3) output projection (all-fp16 mma; fp32 output)
    gemm_mma<512, 256, 0, float><<<dim3(8, 4, BATCH), 256, GEMM_SMEM>>>(
        (const __half*)wah, (const __half*)afp, b_attn, out, 1.0f);
}